// round 1
// baseline (speedup 1.0000x reference)
#include <cuda_runtime.h>
#include <cuda_bf16.h>
#include <cstdint>

// Problem constants
#define BB   32
#define CC   64
#define HH   128
#define WW   128
#define OUTC 64
#define KK   3
#define HID  128
#define WSZ  (OUTC * CC * KK * KK)   // 36864 per-sample weight elements

// Scratch (static device globals — no allocation allowed)
__device__ float g_stats[BB * CC];             // [b][c]
__device__ float g_hidden[BB * HID];           // [b][h]
__device__ float g_weight[(size_t)BB * WSZ];   // permuted: [b][c][o][k]  (k = kh*3+kw)

// ---------------------------------------------------------------------------
// Kernel 1: per-(b,c) spatial mean.  grid=2048 blocks, 256 threads.
// ---------------------------------------------------------------------------
__global__ void stats_kernel(const float* __restrict__ x) {
    int bc = blockIdx.x;  // 0..2047
    const float4* xv = reinterpret_cast<const float4*>(x + (size_t)bc * (HH * WW));
    float s = 0.f;
#pragma unroll
    for (int i = 0; i < 16; ++i) {
        float4 v = xv[threadIdx.x + i * 256];
        s += (v.x + v.y) + (v.z + v.w);
    }
#pragma unroll
    for (int off = 16; off; off >>= 1) s += __shfl_xor_sync(0xffffffffu, s, off);
    __shared__ float red[8];
    if ((threadIdx.x & 31) == 0) red[threadIdx.x >> 5] = s;
    __syncthreads();
    if (threadIdx.x < 8) {
        float t = red[threadIdx.x];
#pragma unroll
        for (int off = 4; off; off >>= 1) t += __shfl_xor_sync(0xffu, t, off);
        if (threadIdx.x == 0) g_stats[bc] = t * (1.0f / (HH * WW));
    }
}

// ---------------------------------------------------------------------------
// Kernel 2: hidden = relu(stats @ W1 + b1).  grid=32, block=128.
// W1 is [C, HID] row-major.
// ---------------------------------------------------------------------------
__global__ void hidden_kernel(const float* __restrict__ W1, const float* __restrict__ b1) {
    int b = blockIdx.x;
    __shared__ float s[CC];
    if (threadIdx.x < CC) s[threadIdx.x] = g_stats[b * CC + threadIdx.x];
    __syncthreads();
    int h = threadIdx.x;
    float acc = b1[h];
#pragma unroll 8
    for (int c = 0; c < CC; ++c) acc += s[c] * W1[c * HID + h];
    g_hidden[b * HID + h] = fmaxf(acc, 0.0f);
}

// ---------------------------------------------------------------------------
// Kernel 3: weight = hidden @ W2 + b2, stored permuted [b][c][o][k].
// W2 is [HID, WSZ] row-major.  Column j of W2 corresponds to (o,c,k):
//   j = o*(CC*KK*KK) + c*(KK*KK) + k
// Each thread: 4 consecutive j (float4 LDG) x 8 b accumulators.
// grid = (WSZ/1024=36, BB/8=4), block=256.
// ---------------------------------------------------------------------------
__global__ void wgen_kernel(const float* __restrict__ W2, const float* __restrict__ b2) {
    __shared__ float sh[8][HID];
    int b0 = blockIdx.y * 8;
    for (int i = threadIdx.x; i < 8 * HID; i += 256)
        sh[i >> 7][i & 127] = g_hidden[(b0 + (i >> 7)) * HID + (i & 127)];
    __syncthreads();

    int j0 = blockIdx.x * 1024 + threadIdx.x * 4;
    float4 acc[8];
#pragma unroll
    for (int bb = 0; bb < 8; ++bb) acc[bb] = make_float4(0.f, 0.f, 0.f, 0.f);

    for (int k = 0; k < HID; ++k) {
        float4 wv = *reinterpret_cast<const float4*>(&W2[(size_t)k * WSZ + j0]);
#pragma unroll
        for (int bb = 0; bb < 8; ++bb) {
            float hv = sh[bb][k];
            acc[bb].x = fmaf(hv, wv.x, acc[bb].x);
            acc[bb].y = fmaf(hv, wv.y, acc[bb].y);
            acc[bb].z = fmaf(hv, wv.z, acc[bb].z);
            acc[bb].w = fmaf(hv, wv.w, acc[bb].w);
        }
    }
    float4 bias = *reinterpret_cast<const float4*>(&b2[j0]);
#pragma unroll
    for (int bb = 0; bb < 8; ++bb) {
        float vals[4] = {acc[bb].x + bias.x, acc[bb].y + bias.y,
                         acc[bb].z + bias.z, acc[bb].w + bias.w};
#pragma unroll
        for (int q = 0; q < 4; ++q) {
            int j = j0 + q;
            int o = j / (CC * KK * KK);
            int rem = j % (CC * KK * KK);
            int c = rem / (KK * KK);
            int k = rem % (KK * KK);
            // permuted layout [b][c][o][k]
            g_weight[(((size_t)(b0 + bb) * CC + c) * OUTC + o) * (KK * KK) + k] = vals[q];
        }
    }
}

// ---------------------------------------------------------------------------
// Kernel 4: the grouped conv.
// grid = (8, 8, 32): (w-tile, h-tile, b).  block = 256 threads.
// Thread (to = tid>>5 in 0..7, tp = tid&31):
//   col  = tp & 15           (one of 16 columns of the 16x16 output tile)
//   rb   = (tp>>4) * 8       (row base: 8 rows per thread)
//   o    = to*8 .. to*8+7    (8 output channels)
// -> 64 accumulators per thread (8 o x 8 rows, fixed column).
// Shared: x tile with halo 18x18 (row stride 18 -> conflict-free LDS pattern),
//         per-c weights 64*9 contiguous (warp-broadcast reads).
// ---------------------------------------------------------------------------
__global__ __launch_bounds__(256, 2)
void conv_kernel(const float* __restrict__ x, float* __restrict__ out) {
    __shared__ float sx[18 * 18];
    __shared__ float sw[OUTC * 9];

    int b  = blockIdx.z;
    int h0 = blockIdx.y * 16;
    int w0 = blockIdx.x * 16;
    int tid = threadIdx.x;
    int tp = tid & 31, to = tid >> 5;
    int col = tp & 15;
    int rb  = (tp >> 4) * 8;

    float acc[8][8];
#pragma unroll
    for (int i = 0; i < 8; ++i)
#pragma unroll
        for (int j = 0; j < 8; ++j) acc[i][j] = 0.f;

    const float* xb = x + (size_t)b * CC * HH * WW;
    const float* wb = g_weight + (size_t)b * WSZ;

    for (int c = 0; c < CC; ++c) {
        __syncthreads();
        // load 18x18 input tile (with zero halo)
        for (int i = tid; i < 18 * 18; i += 256) {
            int rr = i / 18, cc2 = i % 18;
            int gr = h0 + rr - 1, gc = w0 + cc2 - 1;
            float v = 0.f;
            if ((unsigned)gr < (unsigned)HH && (unsigned)gc < (unsigned)WW)
                v = xb[(size_t)c * (HH * WW) + gr * WW + gc];
            sx[i] = v;
        }
        // load 576 contiguous weights for this (b,c): layout [o][k]
        for (int i = tid; i < OUTC * 9; i += 256)
            sw[i] = wb[c * (OUTC * 9) + i];
        __syncthreads();

        // per-thread x registers: 10 rows x 3 cols
        float xr[10][3];
#pragma unroll
        for (int j = 0; j < 10; ++j)
#pragma unroll
            for (int dc = 0; dc < 3; ++dc)
                xr[j][dc] = sx[(rb + j) * 18 + col + dc];

#pragma unroll
        for (int o8 = 0; o8 < 8; ++o8) {
            int o = to * 8 + o8;
            float w9[9];
#pragma unroll
            for (int k = 0; k < 9; ++k) w9[k] = sw[o * 9 + k];
#pragma unroll
            for (int i = 0; i < 8; ++i) {
                float s = acc[o8][i];
#pragma unroll
                for (int dr = 0; dr < 3; ++dr)
#pragma unroll
                    for (int dc = 0; dc < 3; ++dc)
                        s = fmaf(xr[i + dr][dc], w9[dr * 3 + dc], s);
                acc[o8][i] = s;
            }
        }
    }

    // write out: thread covers column (w0+col), rows h0+rb .. h0+rb+7, 8 o's
#pragma unroll
    for (int o8 = 0; o8 < 8; ++o8) {
        int o = to * 8 + o8;
        float* op = out + (((size_t)b * OUTC + o) * HH + (h0 + rb)) * WW + (w0 + col);
#pragma unroll
        for (int i = 0; i < 8; ++i) op[i * WW] = acc[o8][i];
    }
}

// ---------------------------------------------------------------------------
extern "C" void kernel_launch(void* const* d_in, const int* in_sizes, int n_in,
                              void* d_out, int out_size) {
    const float* x  = (const float*)d_in[0];
    const float* W1 = (const float*)d_in[1];
    const float* b1 = (const float*)d_in[2];
    const float* W2 = (const float*)d_in[3];
    const float* b2 = (const float*)d_in[4];
    float* out = (float*)d_out;

    stats_kernel<<<BB * CC, 256>>>(x);
    hidden_kernel<<<BB, HID>>>(W1, b1);
    wgen_kernel<<<dim3(WSZ / 1024, BB / 8), 256>>>(W2, b2);
    conv_kernel<<<dim3(WW / 16, HH / 16, BB), 256>>>(x, out);
}